// round 3
// baseline (speedup 1.0000x reference)
#include <cuda_runtime.h>
#include <cstdint>

#define G     34
#define GP    36
#define NPIX  1156
#define NPAD  1296
#define TPB   320
#define ACT   289
#define HID   64
#define BATCH 1024

// ---- packed f32x2 ops (Blackwell; only reachable via PTX) ----
__device__ __forceinline__ float2 ffma2(float2 a, float2 b, float2 c) {
    float2 d;
    asm("{\n\t.reg .b64 ra, rb, rc;\n\t"
        "mov.b64 ra, {%2, %3};\n\tmov.b64 rb, {%4, %5};\n\tmov.b64 rc, {%6, %7};\n\t"
        "fma.rn.f32x2 rc, ra, rb, rc;\n\tmov.b64 {%0, %1}, rc;\n\t}"
        : "=f"(d.x), "=f"(d.y)
        : "f"(a.x), "f"(a.y), "f"(b.x), "f"(b.y), "f"(c.x), "f"(c.y));
    return d;
}
__device__ __forceinline__ float2 fmul2(float2 a, float2 b) {
    float2 d;
    asm("{\n\t.reg .b64 ra, rb, rc;\n\t"
        "mov.b64 ra, {%2, %3};\n\tmov.b64 rb, {%4, %5};\n\t"
        "mul.rn.f32x2 rc, ra, rb;\n\tmov.b64 {%0, %1}, rc;\n\t}"
        : "=f"(d.x), "=f"(d.y)
        : "f"(a.x), "f"(a.y), "f"(b.x), "f"(b.y));
    return d;
}
__device__ __forceinline__ float2 fadd2(float2 a, float2 b) {
    float2 d;
    asm("{\n\t.reg .b64 ra, rb, rc;\n\t"
        "mov.b64 ra, {%2, %3};\n\tmov.b64 rb, {%4, %5};\n\t"
        "add.rn.f32x2 rc, ra, rb;\n\tmov.b64 {%0, %1}, rc;\n\t}"
        : "=f"(d.x), "=f"(d.y)
        : "f"(a.x), "f"(a.y), "f"(b.x), "f"(b.y));
    return d;
}

__device__ __forceinline__ float max9(const float* p) {
    float m = fmaxf(fmaxf(p[-GP-1], p[-GP]), fmaxf(p[-GP+1], p[-1]));
    m = fmaxf(m, fmaxf(fmaxf(p[0], p[1]),
              fmaxf(p[GP-1], fmaxf(p[GP], p[GP+1]))));
    return m;
}

__global__ __launch_bounds__(TPB, 2)
void ca_kernel(
    const float* __restrict__ cell_g, const float* __restrict__ food_g,
    const float* __restrict__ fc1w,   const float* __restrict__ fc1b,
    const float* __restrict__ fc2w,   const float* __restrict__ fc2b,
    const float* __restrict__ skg,    const int* __restrict__ steps_p,
    float* __restrict__ out)
{
    __shared__ float  cs0[NPAD], cs1[NPAD], cs2[NPAD], cs3[NPAD];  // 36x36 zero-halo
    __shared__ float  xb[NPAD];          // food (init), then raw x0 scratch
    __shared__ float  scp[NPAD];         // padded scent (constant over steps)
    __shared__ float4 w1q[HID][6];       // fc1 weights, duplicated pairs
    __shared__ float4 w2q[HID][2];       // fc2^T weights, duplicated pairs
    __shared__ float2 b1p[HID];
    __shared__ float  sk[361];           // scent kernel (init only; hist overlays)
    __shared__ float  b2s[4];
    __shared__ int    s_cl;
    __shared__ unsigned int s_kk, s_pref, s_zc;
    __shared__ float  s_sum;
    __shared__ int    s_lc;

    unsigned int* hist = (unsigned int*)sk;   // radix hist (slow path only)

    const int b    = blockIdx.x;
    const int tid  = threadIdx.x;
    const int lane = tid & 31;
    const bool act = tid < ACT;
    const float* cellb = cell_g + (size_t)b * 4 * NPIX;
    const float* foodb = food_g + (size_t)b * NPIX;

    for (int idx = tid; idx < NPAD; idx += TPB) {
        cs0[idx] = 0.f; cs1[idx] = 0.f; cs2[idx] = 0.f; cs3[idx] = 0.f;
        xb[idx] = 0.f;  scp[idx] = 0.f;
    }
    if (tid == 0) s_cl = 0;
    __syncthreads();

    for (int idx = tid; idx < 4 * NPIX; idx += TPB) {
        int c = idx / NPIX, p = idx - c * NPIX;
        int i = p / G, j = p - i * G;
        float v = cellb[idx];
        int bi = (i + 1) * GP + (j + 1);
        if (c == 0) cs0[bi] = v; else if (c == 1) cs1[bi] = v;
        else if (c == 2) cs2[bi] = v; else cs3[bi] = v;
    }
    for (int idx = tid; idx < NPIX; idx += TPB) xb[idx] = foodb[idx];   // food (unpadded)
    for (int idx = tid; idx < 768; idx += TPB) {
        float w = fc1w[idx];
        ((float2*)w1q)[idx] = make_float2(w, w);
    }
    for (int idx = tid; idx < 256; idx += TPB) {
        int o = idx >> 6, j = idx & 63;
        float w = fc2w[idx];
        ((float2*)w2q)[j * 4 + o] = make_float2(w, w);
    }
    for (int idx = tid; idx < HID; idx += TPB) {
        float v = fc1b[idx];
        b1p[idx] = make_float2(v, v);
    }
    for (int idx = tid; idx < 361; idx += TPB) sk[idx] = skg[idx];
    if (tid < 4) b2s[tid] = fc2b[tid];

    int steps = steps_p[0];
    if (steps < 0 || steps > 1000000) {        // defensive: steps stored as f32
        float f = __int_as_float(steps);
        steps = (int)f;
    }

    int pbase[4] = {0, 0, 0, 0};
    __syncthreads();

    // ---- scent: 19x19 cross-correlation (constant); initial cl count ----
    int cl0 = 0;
    if (act) {
        #pragma unroll
        for (int k = 0; k < 4; k++) {
            int p = tid + ACT * k;
            int i = p / G, j = p - i * G;
            pbase[k] = (i + 1) * GP + (j + 1);
            float s = 0.f;
            for (int a = 0; a < 19; a++) {
                int ii = i + a - 9;
                if ((unsigned)ii < (unsigned)G) {
                    const float* kr = &sk[a * 19];
                    const float* fr = &xb[ii * G];
                    for (int bb = 0; bb < 19; bb++) {
                        int jj = j + bb - 9;
                        if ((unsigned)jj < (unsigned)G) s = fmaf(kr[bb], fr[jj], s);
                    }
                }
            }
            scp[pbase[k]] = s;
            cl0 += (cs0[pbase[k]] > 0.8f) ? 1 : 0;
        }
    }
    #pragma unroll
    for (int o = 16; o; o >>= 1) cl0 += __shfl_xor_sync(0xffffffffu, cl0, o);
    if (lane == 0 && cl0) atomicAdd(&s_cl, cl0);
    __syncthreads();
    for (int idx = tid; idx < NPAD; idx += TPB) xb[idx] = 0.f;  // xb -> x0 scratch

    // ======================= main step loop =======================
    for (int st = 0; st < steps; ++st) {
        __syncthreads();                                  // S0

        // Phase B: perception + MLP; write raw x0 to xb
        float2 yp[2][12];
        float  X[4][4];
        int    premask = 0;
        if (act) {
            #pragma unroll
            for (int k = 0; k < 4; k++) {
                const int bi = pbase[k];
                float mx = 0.f;
                #pragma unroll
                for (int c = 0; c < 4; c++) {
                    const float* p = (c == 0) ? &cs0[bi] : (c == 1) ? &cs1[bi]
                                   : (c == 2) ? &cs2[bi] : &scp[bi];
                    float n00 = p[-GP-1], n01 = p[-GP], n02 = p[-GP+1];
                    float n10 = p[-1],    n11 = p[0],   n12 = p[1];
                    float n20 = p[GP-1],  n21 = p[GP],  n22 = p[GP+1];
                    float sx = ((n02 - n00) + 2.f * (n12 - n10) + (n22 - n20)) * 0.125f;
                    float sy = ((n20 - n00) + 2.f * (n21 - n01) + (n22 - n02)) * 0.125f;
                    if (c == 0)
                        mx = fmaxf(fmaxf(fmaxf(n00, n01), fmaxf(n02, n10)),
                                   fmaxf(fmaxf(n11, n12),
                                         fmaxf(n20, fmaxf(n21, n22))));
                    if (k & 1) {
                        yp[k >> 1][c].y = n11; yp[k >> 1][4 + c].y = sx; yp[k >> 1][8 + c].y = sy;
                    } else {
                        yp[k >> 1][c].x = n11; yp[k >> 1][4 + c].x = sx; yp[k >> 1][8 + c].x = sy;
                    }
                }
                if (mx > 0.1f) premask |= (1 << k);
            }

            float2 A0[4], A1[4];
            #pragma unroll
            for (int c = 0; c < 4; c++) {
                float bv = b2s[c];
                A0[c] = make_float2(bv, bv);
                A1[c] = make_float2(bv, bv);
            }
            #pragma unroll 2
            for (int j = 0; j < HID; j++) {
                const float4* wr = w1q[j];
                float4 wA = wr[0], wB = wr[1], wC = wr[2],
                       wD = wr[3], wE = wr[4], wF = wr[5];
                float2 bj = b1p[j];
                float2 wl, wh;
                // four independent 6-deep chains
                wl = make_float2(wA.x, wA.y); wh = make_float2(wA.z, wA.w);
                float2 h0a = ffma2(wl, yp[0][0], bj);
                float2 h0b = fmul2(wh, yp[0][1]);
                float2 h1a = ffma2(wl, yp[1][0], bj);
                float2 h1b = fmul2(wh, yp[1][1]);
                wl = make_float2(wB.x, wB.y); wh = make_float2(wB.z, wB.w);
                h0a = ffma2(wl, yp[0][2], h0a); h0b = ffma2(wh, yp[0][3], h0b);
                h1a = ffma2(wl, yp[1][2], h1a); h1b = ffma2(wh, yp[1][3], h1b);
                wl = make_float2(wC.x, wC.y); wh = make_float2(wC.z, wC.w);
                h0a = ffma2(wl, yp[0][4], h0a); h0b = ffma2(wh, yp[0][5], h0b);
                h1a = ffma2(wl, yp[1][4], h1a); h1b = ffma2(wh, yp[1][5], h1b);
                wl = make_float2(wD.x, wD.y); wh = make_float2(wD.z, wD.w);
                h0a = ffma2(wl, yp[0][6], h0a); h0b = ffma2(wh, yp[0][7], h0b);
                h1a = ffma2(wl, yp[1][6], h1a); h1b = ffma2(wh, yp[1][7], h1b);
                wl = make_float2(wE.x, wE.y); wh = make_float2(wE.z, wE.w);
                h0a = ffma2(wl, yp[0][8], h0a); h0b = ffma2(wh, yp[0][9], h0b);
                h1a = ffma2(wl, yp[1][8], h1a); h1b = ffma2(wh, yp[1][9], h1b);
                wl = make_float2(wF.x, wF.y); wh = make_float2(wF.z, wF.w);
                h0a = ffma2(wl, yp[0][10], h0a); h0b = ffma2(wh, yp[0][11], h0b);
                h1a = ffma2(wl, yp[1][10], h1a); h1b = ffma2(wh, yp[1][11], h1b);
                float2 h0 = fadd2(h0a, h0b);
                float2 h1 = fadd2(h1a, h1b);
                h0.x = fmaxf(h0.x, 0.f); h0.y = fmaxf(h0.y, 0.f);
                h1.x = fmaxf(h1.x, 0.f); h1.y = fmaxf(h1.y, 0.f);
                float4 v0 = w2q[j][0], v1 = w2q[j][1];
                float2 u0 = make_float2(v0.x, v0.y), u1 = make_float2(v0.z, v0.w);
                float2 u2 = make_float2(v1.x, v1.y), u3 = make_float2(v1.z, v1.w);
                A0[0] = ffma2(u0, h0, A0[0]); A0[1] = ffma2(u1, h0, A0[1]);
                A0[2] = ffma2(u2, h0, A0[2]); A0[3] = ffma2(u3, h0, A0[3]);
                A1[0] = ffma2(u0, h1, A1[0]); A1[1] = ffma2(u1, h1, A1[1]);
                A1[2] = ffma2(u2, h1, A1[2]); A1[3] = ffma2(u3, h1, A1[3]);
            }
            #pragma unroll
            for (int c = 0; c < 4; c++) {
                X[c][0] = yp[0][c].x + A0[c].x;
                X[c][1] = yp[0][c].y + A0[c].y;
                X[c][2] = yp[1][c].x + A1[c].x;
                X[c][3] = yp[1][c].y + A1[c].y;
            }
            #pragma unroll
            for (int k = 0; k < 4; k++) xb[pbase[k]] = X[0][k];  // raw x0
        }
        if (tid == 0) {
            int k = s_cl; if (k > NPIX - 1) k = NPIX - 1;
            s_kk = (unsigned)k;
            s_pref = 0u; s_zc = 0u; s_cl = 0;
        }
        __syncthreads();                                  // S2

        // Phase C: post mask (raw x0), clip, store; count zeros
        float v0f[4] = {0.f, 0.f, 0.f, 0.f};
        unsigned zc = 0;
        if (act) {
            #pragma unroll
            for (int k = 0; k < 4; k++) {
                const int bi = pbase[k];
                bool keep = ((premask >> k) & 1) && (max9(&xb[bi]) > 0.1f);
                float v0 = keep ? X[0][k] : 0.f;
                float v1 = keep ? X[1][k] : 0.f;
                float v2 = keep ? X[2][k] : 0.f;
                float v3 = keep ? X[3][k] : 0.f;
                v0 = fminf(fmaxf(v0, 0.f), 1.f);
                v1 = fminf(fmaxf(v1, -10.f), 10.f);
                v2 = fminf(fmaxf(v2, -10.f), 10.f);
                v3 = fminf(fmaxf(v3, -10.f), 10.f);
                cs0[bi] = v0; cs1[bi] = v1; cs2[bi] = v2;
                if (st == steps - 1) cs3[bi] = v3;   // chan3 never read in-loop
                v0f[k] = v0;
                zc += (v0 == 0.f) ? 1u : 0u;
            }
        }
        #pragma unroll
        for (int o = 16; o; o >>= 1) zc += __shfl_xor_sync(0xffffffffu, zc, o);
        if (lane == 0 && zc) atomicAdd(&s_zc, zc);
        __syncthreads();                                  // S3

        float kth;
        if (s_kk < s_zc) {
            kth = 0.0f;                                   // fast path: kth value is 0
        } else {
            // exact k-th smallest via 4-pass radix-256 on f32 bits (values >= 0)
            for (int ps = 3; ps >= 0; --ps) {
                const int sh = ps * 8;
                if (tid < 256) hist[tid] = 0u;
                __syncthreads();
                unsigned pref = s_pref;
                if (act) {
                    #pragma unroll
                    for (int k = 0; k < 4; k++) {
                        unsigned bits = __float_as_uint(v0f[k]);
                        bool m = (ps == 3) || ((bits >> (sh + 8)) == (pref >> (sh + 8)));
                        if (m) atomicAdd(&hist[(bits >> sh) & 255u], 1u);
                    }
                }
                __syncthreads();
                if (tid < 32) {
                    unsigned c[8];
                    #pragma unroll
                    for (int i = 0; i < 8; i++) c[i] = hist[lane * 8 + i];
                    unsigned tot = c[0]+c[1]+c[2]+c[3]+c[4]+c[5]+c[6]+c[7];
                    unsigned incl = tot;
                    #pragma unroll
                    for (int o = 1; o < 32; o <<= 1) {
                        unsigned v = __shfl_up_sync(0xffffffffu, incl, o);
                        if (lane >= o) incl += v;
                    }
                    unsigned kk = s_kk;
                    unsigned ball = __ballot_sync(0xffffffffu, incl > kk);
                    int src = __ffs(ball) - 1;
                    if (lane == src) {
                        unsigned cum = incl - tot;
                        #pragma unroll
                        for (int i = 0; i < 8; i++) {
                            if (cum + c[i] > kk) {
                                s_pref = pref | ((unsigned)(lane * 8 + i) << sh);
                                s_kk   = kk - cum;
                                break;
                            }
                            cum += c[i];
                        }
                    }
                }
                __syncthreads();
            }
            kth = __uint_as_float(s_pref);
        }

        // apply select; count next step's cl = count(kept > 0.8)
        int cnt = 0;
        if (act) {
            #pragma unroll
            for (int k = 0; k < 4; k++) {
                if (v0f[k] > kth) {
                    cnt += (v0f[k] > 0.8f) ? 1 : 0;
                } else if (v0f[k] != 0.f) {
                    cs0[pbase[k]] = 0.f;
                }
            }
        }
        #pragma unroll
        for (int o = 16; o; o >>= 1) cnt += __shfl_xor_sync(0xffffffffu, cnt, o);
        if (lane == 0 && cnt) atomicAdd(&s_cl, cnt);
    }

    if (tid == 0) { s_sum = 0.f; s_lc = 0; }
    __syncthreads();

    // ---- outputs: [cell | food | total_pixel_val | living_count] ----
    float* out_cell = out;
    float* out_food = out + (size_t)BATCH * 4 * NPIX;
    float* out_tot  = out + (size_t)BATCH * 5 * NPIX;
    float* out_lc   = out_tot + BATCH;

    for (int idx = tid; idx < 4 * NPIX; idx += TPB) {
        int c = idx / NPIX, p = idx - c * NPIX;
        int i = p / G, j = p - i * G;
        int bi = (i + 1) * GP + (j + 1);
        float v = (c == 0) ? cs0[bi] : (c == 1) ? cs1[bi] : (c == 2) ? cs2[bi] : cs3[bi];
        out_cell[(size_t)b * 4 * NPIX + idx] = v;
    }
    for (int idx = tid; idx < NPIX; idx += TPB)
        out_food[(size_t)b * NPIX + idx] = foodb[idx];

    float psum = 0.f; int plc = 0;
    if (act) {
        #pragma unroll
        for (int k = 0; k < 4; k++) {
            float v = cs0[pbase[k]];
            psum += v;
            plc  += (v > 0.1f) ? 1 : 0;
        }
    }
    #pragma unroll
    for (int o = 16; o; o >>= 1) {
        psum += __shfl_xor_sync(0xffffffffu, psum, o);
        plc  += __shfl_xor_sync(0xffffffffu, plc, o);
    }
    if (lane == 0) {
        atomicAdd(&s_sum, psum);
        atomicAdd(&s_lc, plc);
    }
    __syncthreads();
    if (tid == 0) {
        out_tot[b] = s_sum;
        out_lc[b]  = (float)s_lc;
    }
}

extern "C" void kernel_launch(void* const* d_in, const int* in_sizes, int n_in,
                              void* d_out, int out_size) {
    const float* cell = (const float*)d_in[0];
    const float* food = (const float*)d_in[1];
    const float* fc1w = (const float*)d_in[2];
    const float* fc1b = (const float*)d_in[3];
    const float* fc2w = (const float*)d_in[4];
    const float* fc2b = (const float*)d_in[5];
    const float* skg  = (const float*)d_in[6];
    const int*   stp  = (const int*)d_in[7];
    float* out = (float*)d_out;
    ca_kernel<<<BATCH, TPB>>>(cell, food, fc1w, fc1b, fc2w, fc2b, skg, stp, out);
}